// round 14
// baseline (speedup 1.0000x reference)
#include <cuda_runtime.h>

#define N_BINS 10
#define GRID_BLOCKS 1184    // 148 SMs * 8 blocks -> one wave at full occupancy
#define BLOCK_THREADS 256
#define TOTAL_WARPS (GRID_BLOCKS * (BLOCK_THREADS / 32))

// Global scratch (no allocations allowed). Zero-initialized at module load;
// the last finishing block resets them, so "zeroed at entry" holds across
// graph replays.
__device__ double g_cnt[N_BINS];
__device__ double g_conf[N_BINS];
__device__ double g_acc[N_BINS];
__device__ unsigned g_done;

__device__ __forceinline__ float ex2(float x) {
    float r;
    asm("ex2.approx.f32 %0, %1;" : "=f"(r) : "f"(x));
    return r;
}
// exp(x) with a FIXED instruction sequence (FMUL + MUFU.EX2) so the label
// recompute in the epilogue is bit-identical to the main scan.
__device__ __forceinline__ float expf_fixed(float x) {
    return ex2(__fmul_rn(x, 1.4426950408889634f));
}

// Accumulate 4 elements into (sum, max) in exp domain.
__device__ __forceinline__ void acc4(float4 v, float& s, float& m) {
    float e0 = expf_fixed(v.x);
    float e1 = expf_fixed(v.y);
    float e2 = expf_fixed(v.z);
    float e3 = expf_fixed(v.w);
    s += (e0 + e1) + (e2 + e3);
    m = fmaxf(m, fmaxf(fmaxf(e0, e1), fmaxf(e2, e3)));
}

__global__ void __launch_bounds__(BLOCK_THREADS, 8) ece_fused(
    const float* __restrict__ logits,
    const int* __restrict__ labels,
    int n_rows,
    float* __restrict__ out)
{
    __shared__ float s_c[N_BINS], s_f[N_BINS], s_a[N_BINS];

    const int tid = threadIdx.x;
    if (tid < N_BINS) { s_c[tid] = 0.0f; s_f[tid] = 0.0f; s_a[tid] = 0.0f; }
    __syncthreads();

    const int lane  = tid & 31;
    const int seg   = lane >> 3;         // which of the 4 rows this lane serves
    const int sl    = lane & 7;          // lane within the 8-lane segment
    const int gwarp = blockIdx.x * (BLOCK_THREADS / 32) + (tid >> 5);

    const float4* __restrict__ lrows = (const float4*)logits;

    // 4 rows per warp iteration; lane covers float4 chunks sl, sl+8, sl+16,
    // sl+24 of its row (16 contiguous-ish elements, fully coalesced as a warp).
    const int n_quads = n_rows >> 2;
    int row = gwarp * 4 + seg;
    const float4* __restrict__ p = lrows + (size_t)row * 32 + sl;

    #pragma unroll 1
    for (int q = gwarp; q < n_quads; q += TOTAL_WARPS) {
        float4 v0 = p[0];
        float4 v1 = p[8];
        float4 v2 = p[16];
        float4 v3 = p[24];

        float s = 0.0f, m = 0.0f;        // exps > 0, so 0 acts as -inf
        acc4(v0, s, m);
        acc4(v1, s, m);
        acc4(v2, s, m);
        acc4(v3, s, m);

        // 3-level butterfly inside each 8-lane segment (offsets < 8 never
        // cross segment boundaries; full-constant-mask => real HW SHFL).
        #pragma unroll
        for (int o = 4; o; o >>= 1) {
            s += __shfl_xor_sync(0xffffffffu, s, o);
            m = fmaxf(m, __shfl_xor_sync(0xffffffffu, m, o));
        }

        if (sl == 0) {                   // one epilogue lane per row
            int   lab = __ldg(labels + row);
            float lv  = __ldg(logits + (size_t)row * 128 + lab);  // L1-hot
            float le  = expf_fixed(lv);  // bit-identical recompute

            float conf = __fdividef(m, s);
            int b = min((int)ceilf(conf * 10.0f), N_BINS) - 1;
            b = max(b, 0);
            atomicAdd(&s_c[b], 1.0f);
            atomicAdd(&s_f[b], conf);
            atomicAdd(&s_a[b], (le == m) ? 1.0f : 0.0f);
        }

        p   += (size_t)TOTAL_WARPS * 128;
        row += TOTAL_WARPS * 4;
    }

    // Tail rows [n_quads*4, n_rows): at most 3; handled by gwarp 0, one row
    // per segment, with guarded loads and guarded epilogue.
    if (gwarp == 0 && (n_rows & 3)) {
        int tr = n_quads * 4 + seg;
        bool valid = tr < n_rows;
        const float4* q4 = lrows + (size_t)(valid ? tr : 0) * 32 + sl;
        float4 z = make_float4(0.f, 0.f, 0.f, 0.f);
        float4 v0 = valid ? q4[0]  : z;
        float4 v1 = valid ? q4[8]  : z;
        float4 v2 = valid ? q4[16] : z;
        float4 v3 = valid ? q4[24] : z;
        float s = 0.0f, m = 0.0f;
        acc4(v0, s, m); acc4(v1, s, m); acc4(v2, s, m); acc4(v3, s, m);
        #pragma unroll
        for (int o = 4; o; o >>= 1) {
            s += __shfl_xor_sync(0xffffffffu, s, o);
            m = fmaxf(m, __shfl_xor_sync(0xffffffffu, m, o));
        }
        if (sl == 0 && valid) {
            int   lab = __ldg(labels + tr);
            float lv  = __ldg(logits + (size_t)tr * 128 + lab);
            float le  = expf_fixed(lv);
            float conf = __fdividef(m, s);
            int b = min((int)ceilf(conf * 10.0f), N_BINS) - 1;
            b = max(b, 0);
            atomicAdd(&s_c[b], 1.0f);
            atomicAdd(&s_f[b], conf);
            atomicAdd(&s_a[b], (le == m) ? 1.0f : 0.0f);
        }
    }

    // ---- block -> global reduction ----
    __syncthreads();
    if (tid < N_BINS) {
        atomicAdd(&g_cnt[tid],  (double)s_c[tid]);
        atomicAdd(&g_conf[tid], (double)s_f[tid]);
        atomicAdd(&g_acc[tid],  (double)s_a[tid]);
        __threadfence();               // order bin atomics before done-ticket
    }
    __syncthreads();

    // Last block finalizes and resets scratch for the next graph replay.
    if (tid == 0) {
        unsigned ticket = atomicAdd(&g_done, 1u);
        if (ticket == GRID_BLOCKS - 1) {
            double ece = 0.0, oe = 0.0;
            #pragma unroll
            for (int i = 0; i < N_BINS; i++) {
                double cnt = atomicAdd(&g_cnt[i],  0.0);
                double cf  = atomicAdd(&g_conf[i], 0.0);
                double ac  = atomicAdd(&g_acc[i],  0.0);
                bool nonempty = cnt > 0.0;
                double prop  = cnt / (double)n_rows;
                double denom = nonempty ? cnt : 1.0;
                double accb  = nonempty ? ac / denom : 0.0;
                double cfb   = nonempty ? cf / denom : 0.0;
                double CE    = cfb - accb;
                double absCE = nonempty ? fabs(CE) : 0.0;
                ece += absCE * prop;
                oe  += (nonempty ? cfb * fmax(CE, 0.0) : 0.0) * prop;
                out[1 + i]  = (float)accb;
                out[12 + i] = (float)prop;
                out[22 + i] = (float)absCE;
                g_cnt[i] = 0.0; g_conf[i] = 0.0; g_acc[i] = 0.0;
            }
            out[0]  = (float)ece;
            out[11] = (float)oe;
            g_done = 0u;
            __threadfence();
        }
    }
}

extern "C" void kernel_launch(void* const* d_in, const int* in_sizes, int n_in,
                              void* d_out, int out_size) {
    const float* logits = (const float*)d_in[0];
    const int*   labels = (const int*)d_in[1];
    float*       out    = (float*)d_out;

    int n_rows = in_sizes[0] / 128;   // C = 128

    ece_fused<<<GRID_BLOCKS, BLOCK_THREADS>>>(logits, labels, n_rows, out);
}

// round 15
// speedup vs baseline: 1.1194x; 1.1194x over previous
#include <cuda_runtime.h>

#define N_BINS 10
#define GRID_BLOCKS 888     // 148 SMs * 6 blocks -> one wave at occ 6
#define BLOCK_THREADS 256
#define TOTAL_WARPS (GRID_BLOCKS * (BLOCK_THREADS / 32))

// Global scratch (no allocations allowed). Zero-initialized at module load;
// the last finishing block resets them, so "zeroed at entry" holds across
// graph replays.
__device__ double g_cnt[N_BINS];
__device__ double g_conf[N_BINS];
__device__ double g_acc[N_BINS];
__device__ unsigned g_done;

__device__ __forceinline__ float ex2(float x) {
    float r;
    asm("ex2.approx.f32 %0, %1;" : "=f"(r) : "f"(x));
    return r;
}

// Two rows per warp: lanes 0-15 handle one row, lanes 16-31 the next.
// Cross-lane reduction: full-constant-mask shfl_xor at offsets 8,4,2,1 --
// never crosses the 16-lane boundary, so each half reduces independently
// while every SHFL is a single hardware instruction.
// Each lane holds 8 columns of its row: cols 4*hl..4*hl+3 (A) and
// 64+4*hl..64+4*hl+3 (B). lab = label of THIS lane's row.
// Lane hl of each half accumulates bin hl.
__device__ __forceinline__ void ece_pair(
    float4 A, float4 B, int lab, int hl,
    bool acc_en,
    float& r_cnt, float& r_conf, float& r_acc)
{
    const float L2E = 1.4426950408889634f;
    float e0 = ex2(A.x * L2E);
    float e1 = ex2(A.y * L2E);
    float e2 = ex2(A.z * L2E);
    float e3 = ex2(A.w * L2E);
    float e4 = ex2(B.x * L2E);
    float e5 = ex2(B.y * L2E);
    float e6 = ex2(B.z * L2E);
    float e7 = ex2(B.w * L2E);

    // Local sum + local max of the 8 exps.
    float s = ((e0 + e1) + (e2 + e3)) + ((e4 + e5) + (e6 + e7));
    float m = fmaxf(fmaxf(fmaxf(e0, e1), fmaxf(e2, e3)),
                    fmaxf(fmaxf(e4, e5), fmaxf(e6, e7)));

    // Does MY lane own the label column, and does it attain my local max?
    int sub = lab & 3;
    float elo = (sub & 2) ? ((sub & 1) ? e3 : e2) : ((sub & 1) ? e1 : e0);
    float ehi = (sub & 2) ? ((sub & 1) ? e7 : e6) : ((sub & 1) ? e5 : e4);
    float vl  = (lab & 64) ? ehi : elo;
    unsigned bit = (((lab >> 2) & 15) == hl) && (vl == m);

    // Packed key: exps are positive (bits < 2^31), so (bits<<1)|correct is
    // order-preserving in m.
    unsigned k = (__float_as_uint(m) << 1) | bit;

    // Segmented butterfly reduction within each 16-lane half.
    #pragma unroll
    for (int o = 8; o; o >>= 1) {
        s += __shfl_xor_sync(0xffffffffu, s, o);
        unsigned ok = __shfl_xor_sync(0xffffffffu, k, o);
        k = max(k, ok);
    }
    float wm = __uint_as_float(k >> 1);

    float conf = __fdividef(wm, s);                       // max softmax prob
    int b1 = min((int)ceilf(conf * 10.0f), N_BINS);       // in [1,10]
    if (acc_en && b1 == hl + 1) {
        r_cnt  += 1.0f;
        r_conf += conf;
        r_acc  += (float)(k & 1u);
    }
}

__global__ void __launch_bounds__(BLOCK_THREADS, 6) ece_fused(
    const float* __restrict__ logits,
    const int* __restrict__ labels,
    int n_rows,
    float* __restrict__ out)
{
    __shared__ float s_c[N_BINS], s_f[N_BINS], s_a[N_BINS];

    int tid = threadIdx.x;
    if (tid < N_BINS) { s_c[tid] = 0.0f; s_f[tid] = 0.0f; s_a[tid] = 0.0f; }

    const int lane  = tid & 31;
    const int half  = lane >> 4;           // 0: even row of pair, 1: odd row
    const int hl    = lane & 15;
    const int warp  = tid >> 5;
    const int gwarp = blockIdx.x * (BLOCK_THREADS / 32) + warp;

    const float4* __restrict__ lrows = (const float4*)logits;

    float r_cnt = 0.0f, r_conf = 0.0f, r_acc = 0.0f;

    // 2 pairs (4 rows = 2KB) per iteration: loads hoisted for MLP, loop
    // overhead amortized over two pairs.
    const int n_pairs = n_rows >> 1;
    const int n_quads = n_pairs >> 1;      // iterations of the 2-pair loop
    const float4* __restrict__ p = lrows + (size_t)gwarp * 128 + (half << 5) + hl;
    const int4*   __restrict__ lp = (const int4*)labels + gwarp;

    #pragma unroll 1
    for (int q = gwarp; q < n_quads; q += TOTAL_WARPS) {
        float4 A0 = p[0];
        float4 B0 = p[16];
        float4 A1 = p[64];
        float4 B1 = p[80];
        int4   L  = *lp;
        ece_pair(A0, B0, half ? L.y : L.x, hl, true, r_cnt, r_conf, r_acc);
        ece_pair(A1, B1, half ? L.w : L.z, hl, true, r_cnt, r_conf, r_acc);
        p  += (size_t)TOTAL_WARPS * 128;
        lp += TOTAL_WARPS;
    }

    // Tail pair (n_pairs odd): handled per-pair by warp 0.
    if (gwarp == 0) {
        for (int pr = n_quads * 2; pr < n_pairs; pr++) {
            const float4* q4 = lrows + (size_t)pr * 64 + (half << 5) + hl;
            float4 A = q4[0], B = q4[16];
            int lab = labels[pr * 2 + half];
            ece_pair(A, B, lab, hl, true, r_cnt, r_conf, r_acc);
        }
        // Odd leftover row (n_rows odd): halves mirror the row, half 0 counts.
        if (n_rows & 1) {
            int r = n_rows - 1;
            const float4* q4 = lrows + (size_t)r * 32 + hl;
            float4 A = q4[0], B = q4[16];
            ece_pair(A, B, labels[r], hl, half == 0, r_cnt, r_conf, r_acc);
        }
    }

    // Block reduction: lane hl (<10) of each half holds bin hl partials.
    __syncthreads();                   // also covers the s_* zero-init
    if (hl < N_BINS) {
        atomicAdd(&s_c[hl], r_cnt);
        atomicAdd(&s_f[hl], r_conf);
        atomicAdd(&s_a[hl], r_acc);
    }
    __syncthreads();

    if (tid < N_BINS) {
        atomicAdd(&g_cnt[tid],  (double)s_c[tid]);
        atomicAdd(&g_conf[tid], (double)s_f[tid]);
        atomicAdd(&g_acc[tid],  (double)s_a[tid]);
        __threadfence();               // order bin atomics before done-ticket
    }
    __syncthreads();

    // Last block finalizes and resets scratch for the next graph replay.
    if (tid == 0) {
        unsigned ticket = atomicAdd(&g_done, 1u);
        if (ticket == GRID_BLOCKS - 1) {
            double ece = 0.0, oe = 0.0;
            #pragma unroll
            for (int i = 0; i < N_BINS; i++) {
                double cnt = atomicAdd(&g_cnt[i],  0.0);
                double cf  = atomicAdd(&g_conf[i], 0.0);
                double ac  = atomicAdd(&g_acc[i],  0.0);
                bool nonempty = cnt > 0.0;
                double prop  = cnt / (double)n_rows;
                double denom = nonempty ? cnt : 1.0;
                double accb  = nonempty ? ac / denom : 0.0;
                double cfb   = nonempty ? cf / denom : 0.0;
                double CE    = cfb - accb;
                double absCE = nonempty ? fabs(CE) : 0.0;
                ece += absCE * prop;
                oe  += (nonempty ? cfb * fmax(CE, 0.0) : 0.0) * prop;
                out[1 + i]  = (float)accb;
                out[12 + i] = (float)prop;
                out[22 + i] = (float)absCE;
                g_cnt[i] = 0.0; g_conf[i] = 0.0; g_acc[i] = 0.0;
            }
            out[0]  = (float)ece;
            out[11] = (float)oe;
            g_done = 0u;
            __threadfence();
        }
    }
}

extern "C" void kernel_launch(void* const* d_in, const int* in_sizes, int n_in,
                              void* d_out, int out_size) {
    const float* logits = (const float*)d_in[0];
    const int*   labels = (const int*)d_in[1];
    float*       out    = (float*)d_out;

    int n_rows = in_sizes[0] / 128;   // C = 128

    ece_fused<<<GRID_BLOCKS, BLOCK_THREADS>>>(logits, labels, n_rows, out);
}